// round 1
// baseline (speedup 1.0000x reference)
#include <cuda_runtime.h>

#define BB 64
#define TT 4096
#define DD 256
#define NSPLIT 32
#define ROWS_PER_BLOCK (TT / NSPLIT)   // 128
#define NWARPS 8
#define ROWS_PER_WARP (ROWS_PER_BLOCK / NWARPS)  // 16

// Scratch (allocation-free rule: __device__ globals)
__device__ float g_mids[BB * DD];
__device__ float g_e[(size_t)BB * TT];
__device__ float g_partial[BB * NSPLIT];

// ---------------------------------------------------------------------------
// Kernel 1: mids[b,d] = sum_e W[d,e] * q[b,e].  64 blocks x 256 threads.
// W (256KB) becomes L2-resident after the first wave; tiny kernel.
// ---------------------------------------------------------------------------
__global__ void mids_kernel(const float* __restrict__ q,
                            const float* __restrict__ W) {
    int b = blockIdx.x;
    __shared__ float qs[DD];
    qs[threadIdx.x] = q[b * DD + threadIdx.x];
    __syncthreads();

    int d = threadIdx.x;
    const float4* Wr = (const float4*)(W + (size_t)d * DD);
    float acc = 0.f;
#pragma unroll 8
    for (int e = 0; e < DD / 4; e++) {
        float4 w = Wr[e];
        acc += w.x * qs[4 * e + 0] + w.y * qs[4 * e + 1]
             + w.z * qs[4 * e + 2] + w.w * qs[4 * e + 3];
    }
    g_mids[b * DD + d] = acc;
}

// ---------------------------------------------------------------------------
// Kernel 2: the heavy pass. Streams k (256 MB).
// grid = (NSPLIT, B), block = 256 threads (8 warps), warp-per-row dot.
// Each lane keeps its 8 mids values in registers; 2x LDG.128 per row per lane
// (fully coalesced). tanh->exp->mask on lane 0 (no max pass needed: tanh is
// bounded, so softmax stabilization cancels exactly).
// Deterministic: per-block smem reduction -> g_partial, no float atomics.
// ---------------------------------------------------------------------------
__global__ __launch_bounds__(256) void score_kernel(
        const float* __restrict__ k,
        const float* __restrict__ m,
        const float* __restrict__ bias_p) {
    int split = blockIdx.x;
    int b     = blockIdx.y;
    int warp  = threadIdx.x >> 5;
    int lane  = threadIdx.x & 31;

    const float* mids = g_mids + b * DD;
    float4 w0 = *(const float4*)(mids + lane * 4);         // dims [0,128)
    float4 w1 = *(const float4*)(mids + 128 + lane * 4);   // dims [128,256)
    float bias = *bias_p;

    const float* kb = k + (size_t)b * TT * DD;
    const float* mb = m + (size_t)b * TT;

    int t0 = split * ROWS_PER_BLOCK + warp * ROWS_PER_WARP;
    float esum = 0.f;

    for (int t = t0; t < t0 + ROWS_PER_WARP; t += 4) {
        float acc[4];
#pragma unroll
        for (int r = 0; r < 4; r++) {
            const float4* kr = (const float4*)(kb + (size_t)(t + r) * DD);
            float4 a0 = kr[lane];
            float4 a1 = kr[lane + 32];
            acc[r] = a0.x * w0.x + a0.y * w0.y + a0.z * w0.z + a0.w * w0.w
                   + a1.x * w1.x + a1.y * w1.y + a1.z * w1.z + a1.w * w1.w;
        }
#pragma unroll
        for (int r = 0; r < 4; r++) {
            float a = acc[r];
#pragma unroll
            for (int o = 16; o; o >>= 1)
                a += __shfl_xor_sync(0xffffffffu, a, o);
            if (lane == 0) {
                float s = tanhf(a + bias);
                float e = __expf(s) * mb[t + r];
                g_e[(size_t)b * TT + t + r] = e;
                esum += e;
            }
        }
    }

    // Deterministic block reduction of esum (only lane 0 of each warp holds it)
    __shared__ float wsum[NWARPS];
    if (lane == 0) wsum[warp] = esum;
    __syncthreads();
    if (threadIdx.x == 0) {
        float s = 0.f;
#pragma unroll
        for (int w = 0; w < NWARPS; w++) s += wsum[w];
        g_partial[b * NSPLIT + split] = s;
    }
}

// ---------------------------------------------------------------------------
// Kernel 3: reduce partials per batch, normalize. 64 blocks x 256 threads.
// ---------------------------------------------------------------------------
__global__ void norm_kernel(float* __restrict__ out) {
    int b = blockIdx.x;
    __shared__ float ssum;
    if (threadIdx.x == 0) {
        float s = 0.f;
#pragma unroll
        for (int i = 0; i < NSPLIT; i++) s += g_partial[b * NSPLIT + i];
        ssum = s;
    }
    __syncthreads();
    float inv = 1.f / ssum;

    const float4* e4 = (const float4*)(g_e + (size_t)b * TT);
    float4*       o4 = (float4*)(out + (size_t)b * TT);
    for (int i = threadIdx.x; i < TT / 4; i += blockDim.x) {
        float4 v = e4[i];
        v.x *= inv; v.y *= inv; v.z *= inv; v.w *= inv;
        o4[i] = v;
    }
}

extern "C" void kernel_launch(void* const* d_in, const int* in_sizes, int n_in,
                              void* d_out, int out_size) {
    const float* q    = (const float*)d_in[0];  // [B, D]
    const float* k    = (const float*)d_in[1];  // [B, T, D]
    const float* m    = (const float*)d_in[2];  // [B, T]
    const float* W    = (const float*)d_in[3];  // [D, D]
    const float* bias = (const float*)d_in[4];  // [1]
    float* out = (float*)d_out;                 // [B, T]

    mids_kernel<<<BB, DD>>>(q, W);

    dim3 grid2(NSPLIT, BB);
    score_kernel<<<grid2, 256>>>(k, m, bias);

    norm_kernel<<<BB, 256>>>(out);
}

// round 3
// speedup vs baseline: 1.1266x; 1.1266x over previous
#include <cuda_runtime.h>

#define BB 64
#define TT 4096
#define DD 256
#define ESLICE 8
#define NSPLIT 32
#define ROWS_PER_BLOCK (TT / NSPLIT)   // 128
#define NWARPS 8
#define ROWS_PER_WARP (ROWS_PER_BLOCK / NWARPS)  // 16
#define ROWS_PER_ITER 8

// Scratch (allocation-free rule: __device__ globals)
__device__ float g_midsp[BB * ESLICE * DD];   // partial mids over e-slices
__device__ float g_e[(size_t)BB * TT];
__device__ float g_partial[BB * NSPLIT];

// ---------------------------------------------------------------------------
// Kernel 1: partial mids. grid=(B, ESLICE), 256 threads.
// midsp[b,s,d] = sum_{e in slice s} W[d,e] * q[b,e]
// 512 blocks, 8 independent float4 loads per thread -> latency-hidden.
// ---------------------------------------------------------------------------
__global__ __launch_bounds__(DD) void midsp_kernel(const float* __restrict__ q,
                                                   const float* __restrict__ W) {
    int b = blockIdx.x;
    int s = blockIdx.y;
    __shared__ float qs[32];
    if (threadIdx.x < 32) qs[threadIdx.x] = q[b * DD + s * 32 + threadIdx.x];
    __syncthreads();

    int d = threadIdx.x;
    const float4* Wr = (const float4*)(W + (size_t)d * DD + s * 32);
    float4 w[8];
#pragma unroll
    for (int j = 0; j < 8; j++) w[j] = Wr[j];   // 8 loads in flight
    float acc = 0.f;
#pragma unroll
    for (int j = 0; j < 8; j++) {
        acc += w[j].x * qs[4 * j + 0] + w[j].y * qs[4 * j + 1]
             + w[j].z * qs[4 * j + 2] + w[j].w * qs[4 * j + 3];
    }
    g_midsp[(b * ESLICE + s) * DD + d] = acc;
}

// ---------------------------------------------------------------------------
// Kernel 2: the heavy pass. Streams k (256 MB) with __ldcs.
// grid = (NSPLIT, B), block = 256 threads (8 warps), warp-per-row dot.
// Prologue sums the 8 e-slice partials into per-lane mids registers.
// 8 rows per iteration -> 16 LDG.128 front-batched per warp (deep MLP).
// tanh is bounded => softmax max-subtraction cancels exactly; skip it.
// Deterministic reductions (no float atomics).
// ---------------------------------------------------------------------------
__global__ __launch_bounds__(256) void score_kernel(
        const float* __restrict__ k,
        const float* __restrict__ m,
        const float* __restrict__ bias_p) {
    int split = blockIdx.x;
    int b     = blockIdx.y;
    int warp  = threadIdx.x >> 5;
    int lane  = threadIdx.x & 31;

    // Sum the 8 partial-mids slices: lane holds dims [4*lane,4*lane+4) and
    // [128+4*lane, 128+4*lane+4).
    float4 w0 = make_float4(0.f, 0.f, 0.f, 0.f);
    float4 w1 = make_float4(0.f, 0.f, 0.f, 0.f);
#pragma unroll
    for (int s = 0; s < ESLICE; s++) {
        const float4* p = (const float4*)(g_midsp + (size_t)(b * ESLICE + s) * DD);
        float4 t0 = p[lane];
        float4 t1 = p[lane + 32];
        w0.x += t0.x; w0.y += t0.y; w0.z += t0.z; w0.w += t0.w;
        w1.x += t1.x; w1.y += t1.y; w1.z += t1.z; w1.w += t1.w;
    }
    float bias = *bias_p;

    const float* kb = k + (size_t)b * TT * DD;
    const float* mb = m + (size_t)b * TT;

    int t0 = split * ROWS_PER_BLOCK + warp * ROWS_PER_WARP;
    float esum = 0.f;

    for (int t = t0; t < t0 + ROWS_PER_WARP; t += ROWS_PER_ITER) {
        float acc[ROWS_PER_ITER];
#pragma unroll
        for (int r = 0; r < ROWS_PER_ITER; r++) {
            const float4* kr = (const float4*)(kb + (size_t)(t + r) * DD);
            float4 a0 = __ldcs(kr + lane);        // bytes [0,512) of the row
            float4 a1 = __ldcs(kr + lane + 32);   // bytes [512,1024)
            acc[r] = a0.x * w0.x + a0.y * w0.y + a0.z * w0.z + a0.w * w0.w
                   + a1.x * w1.x + a1.y * w1.y + a1.z * w1.z + a1.w * w1.w;
        }
#pragma unroll
        for (int r = 0; r < ROWS_PER_ITER; r++) {
            float a = acc[r];
#pragma unroll
            for (int o = 16; o; o >>= 1)
                a += __shfl_xor_sync(0xffffffffu, a, o);
            if (lane == 0) {
                float s = tanhf(a + bias);
                float e = __expf(s) * mb[t + r];
                g_e[(size_t)b * TT + t + r] = e;
                esum += e;
            }
        }
    }

    // Deterministic block reduction of esum (lane 0 of each warp holds it)
    __shared__ float wsum[NWARPS];
    if (lane == 0) wsum[warp] = esum;
    __syncthreads();
    if (threadIdx.x == 0) {
        float s = 0.f;
#pragma unroll
        for (int w = 0; w < NWARPS; w++) s += wsum[w];
        g_partial[b * NSPLIT + split] = s;
    }
}

// ---------------------------------------------------------------------------
// Kernel 3: reduce partials per batch, normalize. 64 blocks x 256 threads.
// ---------------------------------------------------------------------------
__global__ __launch_bounds__(256) void norm_kernel(float* __restrict__ out) {
    int b = blockIdx.x;
    __shared__ float ssum;
    if (threadIdx.x == 0) {
        float s = 0.f;
#pragma unroll
        for (int i = 0; i < NSPLIT; i++) s += g_partial[b * NSPLIT + i];
        ssum = s;
    }
    __syncthreads();
    float inv = 1.f / ssum;

    const float4* e4 = (const float4*)(g_e + (size_t)b * TT);
    float4*       o4 = (float4*)(out + (size_t)b * TT);
    for (int i = threadIdx.x; i < TT / 4; i += blockDim.x) {
        float4 v = e4[i];
        v.x *= inv; v.y *= inv; v.z *= inv; v.w *= inv;
        o4[i] = v;
    }
}

extern "C" void kernel_launch(void* const* d_in, const int* in_sizes, int n_in,
                              void* d_out, int out_size) {
    const float* q    = (const float*)d_in[0];  // [B, D]
    const float* k    = (const float*)d_in[1];  // [B, T, D]
    const float* m    = (const float*)d_in[2];  // [B, T]
    const float* W    = (const float*)d_in[3];  // [D, D]
    const float* bias = (const float*)d_in[4];  // [1]
    float* out = (float*)d_out;                 // [B, T]

    dim3 grid1(BB, ESLICE);
    midsp_kernel<<<grid1, DD>>>(q, W);

    dim3 grid2(NSPLIT, BB);
    score_kernel<<<grid2, 256>>>(k, m, bias);

    norm_kernel<<<BB, 256>>>(out);
}

// round 5
// speedup vs baseline: 1.1669x; 1.0358x over previous
#include <cuda_runtime.h>

#define BB 64
#define TT 4096
#define DD 256
#define NSPLIT 8
#define ROWS_PER_BLOCK (TT / NSPLIT)              // 512
#define NWARPS 8
#define ROWS_PER_WARP (ROWS_PER_BLOCK / NWARPS)   // 64
#define RPI 8                                     // rows per iteration

// Scratch (allocation-free rule: __device__ globals; zero-initialized once)
__device__ float g_midsp[BB * NSPLIT * DD];   // partial mids per e-slice
__device__ float g_e[(size_t)BB * TT];        // exp(score)*mask
__device__ float g_esum[BB * NSPLIT];         // per-block esum partials
__device__ int   g_ready[BB];                 // mids production counter
__device__ int   g_done[BB];                  // streaming completion counter

// ---------------------------------------------------------------------------
// Single fused kernel. grid = (NSPLIT=8, B=64) = 512 blocks, 256 threads.
// __launch_bounds__(256,4): 148 SMs x 4 blocks = 592 >= 512 -> whole grid is
// one resident wave, so the inter-block produce/spin barrier cannot deadlock.
//
// Phase 1: block (s,b) computes the e-slice-s partial of mids[b,:].
// Barrier: per-b arrival counter + spin (thread 0 only), all-resident-safe.
// Phase 2: stream k (256 MB, __ldcs), warp-per-row dot, 8 rows/iter
//          (16 LDG.128 in flight). Butterfly-reduce each row; lane r keeps
//          row r -> tanh/exp/mask/store done by 8 lanes in parallel with
//          coalesced 32B m-loads and e-stores. No max pass: tanh is bounded,
//          softmax stabilization cancels exactly.
// Phase 3: last block per b (atomic counter) sums the 8 esum partials in
//          fixed order, normalizes b's row, resets counters for next replay.
// ---------------------------------------------------------------------------
__global__ __launch_bounds__(256, 4) void fused_kernel(
        const float* __restrict__ q,
        const float* __restrict__ k,
        const float* __restrict__ m,
        const float* __restrict__ W,
        const float* __restrict__ bias_p,
        float* __restrict__ out) {
    int s    = blockIdx.x;
    int b    = blockIdx.y;
    int warp = threadIdx.x >> 5;
    int lane = threadIdx.x & 31;
    int d    = threadIdx.x;

    __shared__ float qs[32];
    __shared__ float wsum[NWARPS];
    __shared__ int   lastflag;
    __shared__ float inv_s;

    // ---- Phase 1: partial mids for e-slice s (32 e-values) ----
    if (threadIdx.x < 32) qs[threadIdx.x] = q[b * DD + s * 32 + threadIdx.x];
    __syncthreads();
    {
        const float4* Wr = (const float4*)(W + (size_t)d * DD + s * 32);
        float4 w[8];
#pragma unroll
        for (int j = 0; j < 8; j++) w[j] = Wr[j];   // 8 loads in flight
        float acc = 0.f;
#pragma unroll
        for (int j = 0; j < 8; j++)
            acc += w[j].x * qs[4 * j + 0] + w[j].y * qs[4 * j + 1]
                 + w[j].z * qs[4 * j + 2] + w[j].w * qs[4 * j + 3];
        g_midsp[(b * NSPLIT + s) * DD + d] = acc;
    }
    __threadfence();
    __syncthreads();
    if (threadIdx.x == 0) {
        atomicAdd(&g_ready[b], 1);
        while (((volatile int*)g_ready)[b] < NSPLIT) __nanosleep(64);
    }
    __syncthreads();
    __threadfence();

    // ---- Prologue: sum the 8 partial slices into per-lane mids registers.
    // lane holds dims [4*lane,4*lane+4) and [128+4*lane,128+4*lane+4).
    float4 w0 = make_float4(0.f, 0.f, 0.f, 0.f);
    float4 w1 = make_float4(0.f, 0.f, 0.f, 0.f);
#pragma unroll
    for (int sl = 0; sl < NSPLIT; sl++) {
        const float4* p = (const float4*)(g_midsp + (size_t)(b * NSPLIT + sl) * DD);
        float4 t0 = p[lane];
        float4 t1 = p[lane + 32];
        w0.x += t0.x; w0.y += t0.y; w0.z += t0.z; w0.w += t0.w;
        w1.x += t1.x; w1.y += t1.y; w1.z += t1.z; w1.w += t1.w;
    }
    float bias = *bias_p;

    // ---- Phase 2: stream k ----
    const float* kb = k + (size_t)b * TT * DD;
    const float* mb = m + (size_t)b * TT;

    int t0 = s * ROWS_PER_BLOCK + warp * ROWS_PER_WARP;
    float esum = 0.f;

    for (int t = t0; t < t0 + ROWS_PER_WARP; t += RPI) {
        float acc[RPI];
#pragma unroll
        for (int r = 0; r < RPI; r++) {
            const float4* kr = (const float4*)(kb + (size_t)(t + r) * DD);
            float4 a0 = __ldcs(kr + lane);        // row bytes [0,512)
            float4 a1 = __ldcs(kr + lane + 32);   // row bytes [512,1024)
            acc[r] = a0.x * w0.x + a0.y * w0.y + a0.z * w0.z + a0.w * w0.w
                   + a1.x * w1.x + a1.y * w1.y + a1.z * w1.z + a1.w * w1.w;
        }
        // Butterfly each row; result is warp-uniform, lane r keeps row r.
        float myA = 0.f;
#pragma unroll
        for (int r = 0; r < RPI; r++) {
            float a = acc[r];
#pragma unroll
            for (int o = 16; o; o >>= 1)
                a += __shfl_xor_sync(0xffffffffu, a, o);
            if (lane == r) myA = a;
        }
        // Lanes 0..7 process their row in parallel (coalesced m-load/e-store)
        float e = 0.f;
        if (lane < RPI) {
            float sc = tanhf(myA + bias);
            e = __expf(sc) * mb[t + lane];
            g_e[(size_t)b * TT + t + lane] = e;
        }
        // Deterministic tree-sum of the 8 e values (fixed order)
#pragma unroll
        for (int o = 4; o; o >>= 1)
            e += __shfl_xor_sync(0xffffffffu, e, o);
        if (lane == 0) esum += e;
    }

    // ---- Phase 3: block esum -> partial; last block per b normalizes ----
    if (lane == 0) wsum[warp] = esum;
    __syncthreads();
    if (threadIdx.x == 0) {
        float t = 0.f;
#pragma unroll
        for (int w = 0; w < NWARPS; w++) t += wsum[w];
        g_esum[b * NSPLIT + s] = t;
        __threadfence();
        int old = atomicAdd(&g_done[b], 1);
        lastflag = (old == NSPLIT - 1);
        if (lastflag) {
            float ssum = 0.f;
#pragma unroll
            for (int i = 0; i < NSPLIT; i++) ssum += g_esum[b * NSPLIT + i];
            inv_s = 1.f / ssum;
        }
    }
    __syncthreads();
    if (lastflag) {
        float inv = inv_s;
        const float4* e4 = (const float4*)(g_e + (size_t)b * TT);
        float4*       o4 = (float4*)(out + (size_t)b * TT);
#pragma unroll
        for (int j = 0; j < (TT / 4) / 256; j++) {
            int i = j * 256 + threadIdx.x;
            float4 v = e4[i];
            v.x *= inv; v.y *= inv; v.z *= inv; v.w *= inv;
            o4[i] = v;
        }
        if (threadIdx.x == 0) {           // reset for next graph replay
            g_ready[b] = 0;
            g_done[b]  = 0;
        }
    }
}

extern "C" void kernel_launch(void* const* d_in, const int* in_sizes, int n_in,
                              void* d_out, int out_size) {
    const float* q    = (const float*)d_in[0];  // [B, D]
    const float* k    = (const float*)d_in[1];  // [B, T, D]
    const float* m    = (const float*)d_in[2];  // [B, T]
    const float* W    = (const float*)d_in[3];  // [D, D]
    const float* bias = (const float*)d_in[4];  // [1]
    float* out = (float*)d_out;                 // [B, T]

    dim3 grid(NSPLIT, BB);
    fused_kernel<<<grid, 256>>>(q, k, m, W, bias, out);
}